// round 5
// baseline (speedup 1.0000x reference)
#include <cuda_runtime.h>

#define S3_EPS 1e-6f
#define PI_F     3.14159265358979f
#define HALFPI_F 1.57079632679490f
#define TPB 256

struct Sim3 { float tx,ty,tz, qx,qy,qz,qw, s; };

__device__ __forceinline__ Sim3 ld_sim3(const float4* __restrict__ p, int i) {
    float4 a = __ldg(p + 2 * i);
    float4 b = __ldg(p + 2 * i + 1);
    Sim3 T = {a.x, a.y, a.z, a.w, b.x, b.y, b.z, b.w};
    return T;
}

// atan2(y, x) for y >= 0, result in [0, pi]. ~1e-6 abs error.
__device__ __forceinline__ float fast_atan2_pos(float y, float x) {
    float ax  = fabsf(x);
    float num = fminf(y, ax);
    float den = fmaxf(y, ax);
    float r   = __fdividef(num, den);
    float r2  = r * r;
    float p = -0.0117212f;
    p = fmaf(p, r2,  0.05265332f);
    p = fmaf(p, r2, -0.11643287f);
    p = fmaf(p, r2,  0.19354346f);
    p = fmaf(p, r2, -0.33262347f);
    p = fmaf(p, r2,  0.99997726f);
    float t = p * r;
    if (y > ax)    t = HALFPI_F - t;
    if (x < 0.0f)  t = PI_F - t;
    return t;
}

__device__ __forceinline__ void qrot(float qx, float qy, float qz, float qw,
                                     float vx, float vy, float vz,
                                     float& ox, float& oy, float& oz) {
    float ux = qy * vz - qz * vy;
    float uy = qz * vx - qx * vz;
    float uz = qx * vy - qy * vx;
    float cx = qy * uz - qz * uy;
    float cy = qz * ux - qx * uz;
    float cz = qx * uy - qy * ux;
    ox = vx + 2.0f * (qw * ux + cx);
    oy = vy + 2.0f * (qw * uy + cy);
    oz = vz + 2.0f * (qw * uz + cz);
}

__device__ __forceinline__ Sim3 sim3_inv(const Sim3 T) {
    Sim3 R;
    R.qx = -T.qx; R.qy = -T.qy; R.qz = -T.qz; R.qw = T.qw;
    R.s = __fdividef(1.0f, T.s);
    float rx, ry, rz;
    qrot(R.qx, R.qy, R.qz, R.qw, T.tx, T.ty, T.tz, rx, ry, rz);
    R.tx = -R.s * rx; R.ty = -R.s * ry; R.tz = -R.s * rz;
    return R;
}

__device__ __forceinline__ Sim3 sim3_mul(const Sim3 A, const Sim3 B) {
    Sim3 R;
    float rx, ry, rz;
    qrot(A.qx, A.qy, A.qz, A.qw, B.tx, B.ty, B.tz, rx, ry, rz);
    R.tx = A.tx + A.s * rx;
    R.ty = A.ty + A.s * ry;
    R.tz = A.tz + A.s * rz;
    R.qx = A.qw * B.qx + A.qx * B.qw + A.qy * B.qz - A.qz * B.qy;
    R.qy = A.qw * B.qy - A.qx * B.qz + A.qy * B.qw + A.qz * B.qx;
    R.qz = A.qw * B.qz + A.qx * B.qy - A.qy * B.qx + A.qz * B.qw;
    R.qw = A.qw * B.qw - A.qx * B.qx - A.qy * B.qy - A.qz * B.qz;
    R.s = A.s * B.s;
    return R;
}

__device__ __forceinline__ void sim3_log(const Sim3 T, float r[7]) {
    const float vx = T.qx, vy = T.qy, vz = T.qz, qw = T.qw;
    float nv2 = vx * vx + vy * vy + vz * vz;
    float nv = sqrtf(nv2);
    float theta_r = 2.0f * fast_atan2_pos(nv, qw);
    bool small_r = nv < S3_EPS;
    float fac = small_r ? 2.0f : __fdividef(theta_r, nv);
    float px = fac * vx, py = fac * vy, pz = fac * vz;   // phi
    float sigma = __logf(T.s);
    float theta = fac * nv;                              // == |phi|

    bool sig_small = fabsf(sigma) < S3_EPS;
    bool th_small  = theta < S3_EPS;
    float sg = sig_small ? 1.0f : sigma;
    float th = th_small  ? 1.0f : theta;
    float scale = T.s;
    float th2 = th * th, sg2 = sg * sg;

    float snth, csth;
    __sincosf(th, &snth, &csth);

    float rsg  = __fdividef(1.0f, sg);
    float rth  = __fdividef(1.0f, th);
    float rth2 = rth * rth;

    float C    = sig_small ? 1.0f : (scale - 1.0f) * rsg;
    float A_ss = th_small ? 0.5f          : (1.0f - csth) * rth2;
    float B_ss = th_small ? (1.0f / 6.0f) : (th - snth) * rth2 * rth;
    float a = scale * snth;
    float b = scale * csth;
    float c = th2 + sg2;
    float rc = __fdividef(1.0f, c);
    float A_g = (a * sg + (1.0f - b) * th) * rth * rc;
    float B_g = (C - ((b - 1.0f) * sg + a * th) * rc) * rth2;
    float rsg2 = rsg * rsg;
    float A_ts = ((sg - 1.0f) * scale + 1.0f) * rsg2;
    float B_ts = (scale * (sg2 - 2.0f * sg + 2.0f) - 2.0f) * 0.5f * rsg2 * rsg;
    float A = sig_small ? A_ss : (th_small ? A_ts : A_g);
    float B = sig_small ? B_ss : (th_small ? B_ts : B_g);

    // W = C*I + A*skew(phi) + B*(phi phi^T - |phi|^2 I)
    float pp = px * px + py * py + pz * pz;
    float d  = C - B * pp;
    float m00 = d + B * px * px;
    float m11 = d + B * py * py;
    float m22 = d + B * pz * pz;
    float Bxy = B * px * py, Bxz = B * px * pz, Byz = B * py * pz;
    float Ax = A * px, Ay = A * py, Az = A * pz;
    float m01 = Bxy - Az, m10 = Bxy + Az;
    float m02 = Bxz + Ay, m20 = Bxz - Ay;
    float m12 = Byz - Ax, m21 = Byz + Ax;

    float a00 = m11 * m22 - m12 * m21;
    float a01 = m02 * m21 - m01 * m22;
    float a02 = m01 * m12 - m02 * m11;
    float a10 = m12 * m20 - m10 * m22;
    float a11 = m00 * m22 - m02 * m20;
    float a12 = m02 * m10 - m00 * m12;
    float a20 = m10 * m21 - m11 * m20;
    float a21 = m01 * m20 - m00 * m21;
    float a22 = m00 * m11 - m01 * m10;
    float det = m00 * a00 + m01 * a10 + m02 * a20;
    float rdet = __fdividef(1.0f, det);

    r[0] = (a00 * T.tx + a01 * T.ty + a02 * T.tz) * rdet;
    r[1] = (a10 * T.tx + a11 * T.ty + a12 * T.tz) * rdet;
    r[2] = (a20 * T.tx + a21 * T.ty + a22 * T.tz) * rdet;
    r[3] = px;
    r[4] = py;
    r[5] = pz;
    r[6] = sigma;
}

__global__ void __launch_bounds__(TPB, 5)
pgo_residual_kernel(const float4* __restrict__ Twc,
                    const float4* __restrict__ Twc_prior_inv,
                    const float4* __restrict__ Todom_inv,
                    const float* __restrict__ prior_w,
                    const float* __restrict__ odom_w,
                    const int2* __restrict__ edges,
                    const float4* __restrict__ T_lc,
                    float* __restrict__ out,
                    int n) {
    __shared__ float s_pw[TPB * 7];
    __shared__ float s_ow[TPB * 7];
    __shared__ float s_out[TPB * 7];

    const int tid  = threadIdx.x;
    const int base = blockIdx.x * TPB;
    const int nblk = min(TPB, n - base);        // valid elements in this block
    const int nfl  = nblk * 7;                  // valid floats
    const int nf4  = nfl >> 2;                  // full float4s

    // Cooperative, coalesced staging of the 28B-record weight arrays.
    {
        const float4* pw4 = (const float4*)(prior_w + (size_t)base * 7);
        const float4* ow4 = (const float4*)(odom_w  + (size_t)base * 7);
        float4* spw4 = (float4*)s_pw;
        float4* sow4 = (float4*)s_ow;
        for (int k = tid; k < nf4; k += TPB) {
            spw4[k] = __ldg(pw4 + k);
            sow4[k] = __ldg(ow4 + k);
        }
        for (int k = (nf4 << 2) + tid; k < nfl; k += TPB) {
            s_pw[k] = __ldg(prior_w + (size_t)base * 7 + k);
            s_ow[k] = __ldg(odom_w  + (size_t)base * 7 + k);
        }
    }
    __syncthreads();

    // Clamp so tail-block threads compute (discarded) valid-address work and
    // still reach the barriers.
    const int i = min(base + tid, n - 1);

    // Long dependent-load chain first (edge indices -> random gathers).
    int2 e = __ldg(edges + i);
    Sim3 Ta  = ld_sim3(Twc, e.x);
    Sim3 Tb  = ld_sim3(Twc, e.y);
    Sim3 Tlc = ld_sim3(T_lc, i);

    Sim3 Ti = ld_sim3(Twc, i);
    Sim3 Tj = ld_sim3(Twc, i + 1);
    Sim3 delta = sim3_mul(sim3_inv(Ti), Tj);

    float acc[7];
    float tmp[7];

    // r_prior
    sim3_log(sim3_mul(delta, ld_sim3(Twc_prior_inv, i)), tmp);
    #pragma unroll
    for (int k = 0; k < 7; k++)
        acc[k] = tmp[k] * s_pw[tid * 7 + k];

    // r_odom
    sim3_log(sim3_mul(delta, ld_sim3(Todom_inv, i)), tmp);
    #pragma unroll
    for (int k = 0; k < 7; k++)
        acc[k] += tmp[k] * s_ow[tid * 7 + k];

    // r_lc
    Sim3 dlc = sim3_mul(sim3_inv(Ta), Tb);
    sim3_log(sim3_mul(dlc, Tlc), tmp);
    #pragma unroll
    for (int k = 0; k < 7; k++)
        acc[k] += tmp[k];

    // Stage output through smem, then coalesced float4 stores.
    #pragma unroll
    for (int k = 0; k < 7; k++)
        s_out[tid * 7 + k] = acc[k];
    __syncthreads();

    {
        float* op = out + (size_t)base * 7;
        float4* op4 = (float4*)op;
        const float4* so4 = (const float4*)s_out;
        for (int k = tid; k < nf4; k += TPB)
            op4[k] = so4[k];
        for (int k = (nf4 << 2) + tid; k < nfl; k += TPB)
            op[k] = s_out[k];
    }
}

extern "C" void kernel_launch(void* const* d_in, const int* in_sizes, int n_in,
                              void* d_out, int out_size) {
    const float4* Twc           = (const float4*)d_in[0];
    const float4* Twc_prior_inv = (const float4*)d_in[1];
    const float4* Todom_inv     = (const float4*)d_in[2];
    const float*  prior_w       = (const float*)d_in[3];
    const float*  odom_w        = (const float*)d_in[4];
    const int2*   edges         = (const int2*)d_in[5];
    const float4* T_lc          = (const float4*)d_in[6];
    float* out = (float*)d_out;

    int n = in_sizes[3] / 7;   // (N_FRAME-1) rows
    int blocks = (n + TPB - 1) / TPB;
    pgo_residual_kernel<<<blocks, TPB>>>(Twc, Twc_prior_inv, Todom_inv,
                                         prior_w, odom_w, edges, T_lc,
                                         out, n);
}

// round 6
// speedup vs baseline: 1.0405x; 1.0405x over previous
#include <cuda_runtime.h>

#define S3_EPS 1e-6f
#define PI_F     3.14159265358979f
#define HALFPI_F 1.57079632679490f
#define TPB 256

struct Sim3 { float tx,ty,tz, qx,qy,qz,qw, s; };

__device__ __forceinline__ Sim3 ld_sim3(const float4* __restrict__ p, int i) {
    float4 a = __ldg(p + 2 * i);
    float4 b = __ldg(p + 2 * i + 1);
    Sim3 T = {a.x, a.y, a.z, a.w, b.x, b.y, b.z, b.w};
    return T;
}

// atan2(y, x) for y >= 0, result in [0, pi]. ~1e-6 abs error.
__device__ __forceinline__ float fast_atan2_pos(float y, float x) {
    float ax  = fabsf(x);
    float num = fminf(y, ax);
    float den = fmaxf(y, ax);
    float r   = __fdividef(num, den);
    float r2  = r * r;
    float p = -0.0117212f;
    p = fmaf(p, r2,  0.05265332f);
    p = fmaf(p, r2, -0.11643287f);
    p = fmaf(p, r2,  0.19354346f);
    p = fmaf(p, r2, -0.33262347f);
    p = fmaf(p, r2,  0.99997726f);
    float t = p * r;
    if (y > ax)    t = HALFPI_F - t;
    if (x < 0.0f)  t = PI_F - t;
    return t;
}

__device__ __forceinline__ void qrot(float qx, float qy, float qz, float qw,
                                     float vx, float vy, float vz,
                                     float& ox, float& oy, float& oz) {
    float ux = qy * vz - qz * vy;
    float uy = qz * vx - qx * vz;
    float uz = qx * vy - qy * vx;
    float cx = qy * uz - qz * uy;
    float cy = qz * ux - qx * uz;
    float cz = qx * uy - qy * ux;
    ox = vx + 2.0f * (qw * ux + cx);
    oy = vy + 2.0f * (qw * uy + cy);
    oz = vz + 2.0f * (qw * uz + cz);
}

__device__ __forceinline__ Sim3 sim3_inv(const Sim3 T) {
    Sim3 R;
    R.qx = -T.qx; R.qy = -T.qy; R.qz = -T.qz; R.qw = T.qw;
    R.s = __fdividef(1.0f, T.s);
    float rx, ry, rz;
    qrot(R.qx, R.qy, R.qz, R.qw, T.tx, T.ty, T.tz, rx, ry, rz);
    R.tx = -R.s * rx; R.ty = -R.s * ry; R.tz = -R.s * rz;
    return R;
}

__device__ __forceinline__ Sim3 sim3_mul(const Sim3 A, const Sim3 B) {
    Sim3 R;
    float rx, ry, rz;
    qrot(A.qx, A.qy, A.qz, A.qw, B.tx, B.ty, B.tz, rx, ry, rz);
    R.tx = A.tx + A.s * rx;
    R.ty = A.ty + A.s * ry;
    R.tz = A.tz + A.s * rz;
    R.qx = A.qw * B.qx + A.qx * B.qw + A.qy * B.qz - A.qz * B.qy;
    R.qy = A.qw * B.qy - A.qx * B.qz + A.qy * B.qw + A.qz * B.qx;
    R.qz = A.qw * B.qz + A.qx * B.qy - A.qy * B.qx + A.qz * B.qw;
    R.qw = A.qw * B.qw - A.qx * B.qx - A.qy * B.qy - A.qz * B.qz;
    R.s = A.s * B.s;
    return R;
}

__device__ __forceinline__ void sim3_log(const Sim3 T, float r[7]) {
    const float vx = T.qx, vy = T.qy, vz = T.qz, qw = T.qw;
    float nv2 = vx * vx + vy * vy + vz * vz;
    float nv = sqrtf(nv2);
    float theta_r = 2.0f * fast_atan2_pos(nv, qw);
    bool small_r = nv < S3_EPS;
    float fac = small_r ? 2.0f : __fdividef(theta_r, nv);
    float px = fac * vx, py = fac * vy, pz = fac * vz;   // phi
    float sigma = __logf(T.s);
    float theta = fac * nv;                              // == |phi|

    bool sig_small = fabsf(sigma) < S3_EPS;
    bool th_small  = theta < S3_EPS;
    float sg = sig_small ? 1.0f : sigma;
    float th = th_small  ? 1.0f : theta;
    float scale = T.s;
    float th2 = th * th, sg2 = sg * sg;

    float snth, csth;
    __sincosf(th, &snth, &csth);

    float rsg  = __fdividef(1.0f, sg);
    float rth  = __fdividef(1.0f, th);
    float rth2 = rth * rth;

    float C    = sig_small ? 1.0f : (scale - 1.0f) * rsg;
    float A_ss = th_small ? 0.5f          : (1.0f - csth) * rth2;
    float B_ss = th_small ? (1.0f / 6.0f) : (th - snth) * rth2 * rth;
    float a = scale * snth;
    float b = scale * csth;
    float c = th2 + sg2;
    float rc = __fdividef(1.0f, c);
    float A_g = (a * sg + (1.0f - b) * th) * rth * rc;
    float B_g = (C - ((b - 1.0f) * sg + a * th) * rc) * rth2;
    float rsg2 = rsg * rsg;
    float A_ts = ((sg - 1.0f) * scale + 1.0f) * rsg2;
    float B_ts = (scale * (sg2 - 2.0f * sg + 2.0f) - 2.0f) * 0.5f * rsg2 * rsg;
    float A = sig_small ? A_ss : (th_small ? A_ts : A_g);
    float B = sig_small ? B_ss : (th_small ? B_ts : B_g);

    // W = C*I + A*skew(phi) + B*(phi phi^T - |phi|^2 I)
    float pp = px * px + py * py + pz * pz;
    float d  = C - B * pp;
    float m00 = d + B * px * px;
    float m11 = d + B * py * py;
    float m22 = d + B * pz * pz;
    float Bxy = B * px * py, Bxz = B * px * pz, Byz = B * py * pz;
    float Ax = A * px, Ay = A * py, Az = A * pz;
    float m01 = Bxy - Az, m10 = Bxy + Az;
    float m02 = Bxz + Ay, m20 = Bxz - Ay;
    float m12 = Byz - Ax, m21 = Byz + Ax;

    float a00 = m11 * m22 - m12 * m21;
    float a01 = m02 * m21 - m01 * m22;
    float a02 = m01 * m12 - m02 * m11;
    float a10 = m12 * m20 - m10 * m22;
    float a11 = m00 * m22 - m02 * m20;
    float a12 = m02 * m10 - m00 * m12;
    float a20 = m10 * m21 - m11 * m20;
    float a21 = m01 * m20 - m00 * m21;
    float a22 = m00 * m11 - m01 * m10;
    float det = m00 * a00 + m01 * a10 + m02 * a20;
    float rdet = __fdividef(1.0f, det);

    r[0] = (a00 * T.tx + a01 * T.ty + a02 * T.tz) * rdet;
    r[1] = (a10 * T.tx + a11 * T.ty + a12 * T.tz) * rdet;
    r[2] = (a20 * T.tx + a21 * T.ty + a22 * T.tz) * rdet;
    r[3] = px;
    r[4] = py;
    r[5] = pz;
    r[6] = sigma;
}

__global__ void __launch_bounds__(TPB)
pgo_residual_kernel(const float4* __restrict__ Twc,
                    const float4* __restrict__ Twc_prior_inv,
                    const float4* __restrict__ Todom_inv,
                    const float* __restrict__ prior_w,
                    const float* __restrict__ odom_w,
                    const int2* __restrict__ edges,
                    const float4* __restrict__ T_lc,
                    float* __restrict__ out,
                    int n) {
    __shared__ float s_pw[TPB * 7];
    __shared__ float s_ow[TPB * 7];
    __shared__ float s_out[TPB * 7];

    const int tid  = threadIdx.x;
    const int base = blockIdx.x * TPB;
    const int nblk = min(TPB, n - base);        // valid elements in this block
    const int nfl  = nblk * 7;                  // valid floats
    const int nf4  = nfl >> 2;                  // full float4s

    // Clamp so tail-block threads do valid-address (discarded) work and reach
    // the barriers.
    const int i = min(base + tid, n - 1);

    // Issue the long dependent-load chain (edge indices -> random gathers)
    // FIRST, so its latency overlaps the staging copy + barrier below.
    int2 e = __ldg(edges + i);
    Sim3 Ta  = ld_sim3(Twc, e.x);
    Sim3 Tb  = ld_sim3(Twc, e.y);
    Sim3 Tlc = ld_sim3(T_lc, i);
    Sim3 Ti  = ld_sim3(Twc, i);
    Sim3 Tj  = ld_sim3(Twc, i + 1);

    // Cooperative, coalesced staging of the 28B-record weight arrays.
    {
        const float4* pw4 = (const float4*)(prior_w + (size_t)base * 7);
        const float4* ow4 = (const float4*)(odom_w  + (size_t)base * 7);
        float4* spw4 = (float4*)s_pw;
        float4* sow4 = (float4*)s_ow;
        for (int k = tid; k < nf4; k += TPB) {
            spw4[k] = __ldg(pw4 + k);
            sow4[k] = __ldg(ow4 + k);
        }
        for (int k = (nf4 << 2) + tid; k < nfl; k += TPB) {
            s_pw[k] = __ldg(prior_w + (size_t)base * 7 + k);
            s_ow[k] = __ldg(odom_w  + (size_t)base * 7 + k);
        }
    }
    __syncthreads();

    Sim3 delta = sim3_mul(sim3_inv(Ti), Tj);

    float acc[7];
    float tmp[7];

    // r_prior
    sim3_log(sim3_mul(delta, ld_sim3(Twc_prior_inv, i)), tmp);
    #pragma unroll
    for (int k = 0; k < 7; k++)
        acc[k] = tmp[k] * s_pw[tid * 7 + k];

    // r_odom
    sim3_log(sim3_mul(delta, ld_sim3(Todom_inv, i)), tmp);
    #pragma unroll
    for (int k = 0; k < 7; k++)
        acc[k] += tmp[k] * s_ow[tid * 7 + k];

    // r_lc
    Sim3 dlc = sim3_mul(sim3_inv(Ta), Tb);
    sim3_log(sim3_mul(dlc, Tlc), tmp);
    #pragma unroll
    for (int k = 0; k < 7; k++)
        acc[k] += tmp[k];

    // Stage output through smem, then coalesced float4 stores.
    #pragma unroll
    for (int k = 0; k < 7; k++)
        s_out[tid * 7 + k] = acc[k];
    __syncthreads();

    {
        float* op = out + (size_t)base * 7;
        float4* op4 = (float4*)op;
        const float4* so4 = (const float4*)s_out;
        for (int k = tid; k < nf4; k += TPB)
            op4[k] = so4[k];
        for (int k = (nf4 << 2) + tid; k < nfl; k += TPB)
            op[k] = s_out[k];
    }
}

extern "C" void kernel_launch(void* const* d_in, const int* in_sizes, int n_in,
                              void* d_out, int out_size) {
    const float4* Twc           = (const float4*)d_in[0];
    const float4* Twc_prior_inv = (const float4*)d_in[1];
    const float4* Todom_inv     = (const float4*)d_in[2];
    const float*  prior_w       = (const float*)d_in[3];
    const float*  odom_w        = (const float*)d_in[4];
    const int2*   edges         = (const int2*)d_in[5];
    const float4* T_lc          = (const float4*)d_in[6];
    float* out = (float*)d_out;

    int n = in_sizes[3] / 7;   // (N_FRAME-1) rows
    int blocks = (n + TPB - 1) / TPB;
    pgo_residual_kernel<<<blocks, TPB>>>(Twc, Twc_prior_inv, Todom_inv,
                                         prior_w, odom_w, edges, T_lc,
                                         out, n);
}

// round 7
// speedup vs baseline: 1.0474x; 1.0066x over previous
#include <cuda_runtime.h>

#define S3_EPS 1e-6f
#define PI_F     3.14159265358979f
#define HALFPI_F 1.57079632679490f
#define TPB 128

struct Sim3 { float tx,ty,tz, qx,qy,qz,qw, s; };

__device__ __forceinline__ Sim3 ld_sim3(const float4* __restrict__ p, int i) {
    float4 a = __ldg(p + 2 * i);
    float4 b = __ldg(p + 2 * i + 1);
    Sim3 T = {a.x, a.y, a.z, a.w, b.x, b.y, b.z, b.w};
    return T;
}

// atan2(y, x) for y >= 0, result in [0, pi]. ~1e-6 abs error.
__device__ __forceinline__ float fast_atan2_pos(float y, float x) {
    float ax  = fabsf(x);
    float num = fminf(y, ax);
    float den = fmaxf(y, ax);
    float r   = __fdividef(num, den);
    float r2  = r * r;
    float p = -0.0117212f;
    p = fmaf(p, r2,  0.05265332f);
    p = fmaf(p, r2, -0.11643287f);
    p = fmaf(p, r2,  0.19354346f);
    p = fmaf(p, r2, -0.33262347f);
    p = fmaf(p, r2,  0.99997726f);
    float t = p * r;
    if (y > ax)    t = HALFPI_F - t;
    if (x < 0.0f)  t = PI_F - t;
    return t;
}

__device__ __forceinline__ void qrot(float qx, float qy, float qz, float qw,
                                     float vx, float vy, float vz,
                                     float& ox, float& oy, float& oz) {
    float ux = qy * vz - qz * vy;
    float uy = qz * vx - qx * vz;
    float uz = qx * vy - qy * vx;
    float cx = qy * uz - qz * uy;
    float cy = qz * ux - qx * uz;
    float cz = qx * uy - qy * ux;
    ox = vx + 2.0f * (qw * ux + cx);
    oy = vy + 2.0f * (qw * uy + cy);
    oz = vz + 2.0f * (qw * uz + cz);
}

__device__ __forceinline__ Sim3 sim3_inv(const Sim3 T) {
    Sim3 R;
    R.qx = -T.qx; R.qy = -T.qy; R.qz = -T.qz; R.qw = T.qw;
    R.s = __fdividef(1.0f, T.s);
    float rx, ry, rz;
    qrot(R.qx, R.qy, R.qz, R.qw, T.tx, T.ty, T.tz, rx, ry, rz);
    R.tx = -R.s * rx; R.ty = -R.s * ry; R.tz = -R.s * rz;
    return R;
}

__device__ __forceinline__ Sim3 sim3_mul(const Sim3 A, const Sim3 B) {
    Sim3 R;
    float rx, ry, rz;
    qrot(A.qx, A.qy, A.qz, A.qw, B.tx, B.ty, B.tz, rx, ry, rz);
    R.tx = A.tx + A.s * rx;
    R.ty = A.ty + A.s * ry;
    R.tz = A.tz + A.s * rz;
    R.qx = A.qw * B.qx + A.qx * B.qw + A.qy * B.qz - A.qz * B.qy;
    R.qy = A.qw * B.qy - A.qx * B.qz + A.qy * B.qw + A.qz * B.qx;
    R.qz = A.qw * B.qz + A.qx * B.qy - A.qy * B.qx + A.qz * B.qw;
    R.qw = A.qw * B.qw - A.qx * B.qx - A.qy * B.qy - A.qz * B.qz;
    R.s = A.s * B.s;
    return R;
}

__device__ __forceinline__ void sim3_log(const Sim3 T, float r[7]) {
    const float vx = T.qx, vy = T.qy, vz = T.qz, qw = T.qw;
    float nv2 = vx * vx + vy * vy + vz * vz;
    float nv = sqrtf(nv2);
    float theta_r = 2.0f * fast_atan2_pos(nv, qw);
    bool small_r = nv < S3_EPS;
    float fac = small_r ? 2.0f : __fdividef(theta_r, nv);
    float px = fac * vx, py = fac * vy, pz = fac * vz;   // phi
    float sigma = __logf(T.s);
    float theta = fac * nv;                              // == |phi|

    bool sig_small = fabsf(sigma) < S3_EPS;
    bool th_small  = theta < S3_EPS;
    float sg = sig_small ? 1.0f : sigma;
    float th = th_small  ? 1.0f : theta;
    float scale = T.s;
    float th2 = th * th, sg2 = sg * sg;

    float snth, csth;
    __sincosf(th, &snth, &csth);

    float rsg  = __fdividef(1.0f, sg);
    float rth  = __fdividef(1.0f, th);
    float rth2 = rth * rth;

    float C    = sig_small ? 1.0f : (scale - 1.0f) * rsg;
    float A_ss = th_small ? 0.5f          : (1.0f - csth) * rth2;
    float B_ss = th_small ? (1.0f / 6.0f) : (th - snth) * rth2 * rth;
    float a = scale * snth;
    float b = scale * csth;
    float c = th2 + sg2;
    float rc = __fdividef(1.0f, c);
    float A_g = (a * sg + (1.0f - b) * th) * rth * rc;
    float B_g = (C - ((b - 1.0f) * sg + a * th) * rc) * rth2;
    float rsg2 = rsg * rsg;
    float A_ts = ((sg - 1.0f) * scale + 1.0f) * rsg2;
    float B_ts = (scale * (sg2 - 2.0f * sg + 2.0f) - 2.0f) * 0.5f * rsg2 * rsg;
    float A = sig_small ? A_ss : (th_small ? A_ts : A_g);
    float B = sig_small ? B_ss : (th_small ? B_ts : B_g);

    // W = C*I + A*skew(phi) + B*(phi phi^T - |phi|^2 I)
    float pp = px * px + py * py + pz * pz;
    float d  = C - B * pp;
    float m00 = d + B * px * px;
    float m11 = d + B * py * py;
    float m22 = d + B * pz * pz;
    float Bxy = B * px * py, Bxz = B * px * pz, Byz = B * py * pz;
    float Ax = A * px, Ay = A * py, Az = A * pz;
    float m01 = Bxy - Az, m10 = Bxy + Az;
    float m02 = Bxz + Ay, m20 = Bxz - Ay;
    float m12 = Byz - Ax, m21 = Byz + Ax;

    float a00 = m11 * m22 - m12 * m21;
    float a01 = m02 * m21 - m01 * m22;
    float a02 = m01 * m12 - m02 * m11;
    float a10 = m12 * m20 - m10 * m22;
    float a11 = m00 * m22 - m02 * m20;
    float a12 = m02 * m10 - m00 * m12;
    float a20 = m10 * m21 - m11 * m20;
    float a21 = m01 * m20 - m00 * m21;
    float a22 = m00 * m11 - m01 * m10;
    float det = m00 * a00 + m01 * a10 + m02 * a20;
    float rdet = __fdividef(1.0f, det);

    r[0] = (a00 * T.tx + a01 * T.ty + a02 * T.tz) * rdet;
    r[1] = (a10 * T.tx + a11 * T.ty + a12 * T.tz) * rdet;
    r[2] = (a20 * T.tx + a21 * T.ty + a22 * T.tz) * rdet;
    r[3] = px;
    r[4] = py;
    r[5] = pz;
    r[6] = sigma;
}

__global__ void __launch_bounds__(TPB)
pgo_residual_kernel(const float4* __restrict__ Twc,
                    const float4* __restrict__ Twc_prior_inv,
                    const float4* __restrict__ Todom_inv,
                    const float* __restrict__ prior_w,
                    const float* __restrict__ odom_w,
                    const int2* __restrict__ edges,
                    const float4* __restrict__ T_lc,
                    float* __restrict__ out,
                    int n) {
    int i = blockIdx.x * TPB + threadIdx.x;
    if (i >= n) return;

    float acc[7];
    float tmp[7];

    // --- r_lc FIRST: the gather chain is issued at the top and consumed
    // immediately, so Ta/Tb/Tlc are dead before the prior/odom logs run.
    {
        int2 e = __ldg(edges + i);
        Sim3 Ta  = ld_sim3(Twc, e.x);
        Sim3 Tb  = ld_sim3(Twc, e.y);
        Sim3 Tlc = ld_sim3(T_lc, i);
        Sim3 dlc = sim3_mul(sim3_inv(Ta), Tb);
        sim3_log(sim3_mul(dlc, Tlc), acc);
    }

    Sim3 Ti = ld_sim3(Twc, i);
    Sim3 Tj = ld_sim3(Twc, i + 1);
    Sim3 delta = sim3_mul(sim3_inv(Ti), Tj);

    // r_prior
    sim3_log(sim3_mul(delta, ld_sim3(Twc_prior_inv, i)), tmp);
    #pragma unroll
    for (int k = 0; k < 7; k++)
        acc[k] += tmp[k] * __ldg(prior_w + 7 * i + k);

    // r_odom
    sim3_log(sim3_mul(delta, ld_sim3(Todom_inv, i)), tmp);
    #pragma unroll
    for (int k = 0; k < 7; k++)
        acc[k] += tmp[k] * __ldg(odom_w + 7 * i + k);

    #pragma unroll
    for (int k = 0; k < 7; k++)
        out[7 * i + k] = acc[k];
}

extern "C" void kernel_launch(void* const* d_in, const int* in_sizes, int n_in,
                              void* d_out, int out_size) {
    const float4* Twc           = (const float4*)d_in[0];
    const float4* Twc_prior_inv = (const float4*)d_in[1];
    const float4* Todom_inv     = (const float4*)d_in[2];
    const float*  prior_w       = (const float*)d_in[3];
    const float*  odom_w        = (const float*)d_in[4];
    const int2*   edges         = (const int2*)d_in[5];
    const float4* T_lc          = (const float4*)d_in[6];
    float* out = (float*)d_out;

    int n = in_sizes[3] / 7;   // (N_FRAME-1) rows
    int blocks = (n + TPB - 1) / TPB;
    pgo_residual_kernel<<<blocks, TPB>>>(Twc, Twc_prior_inv, Todom_inv,
                                         prior_w, odom_w, edges, T_lc,
                                         out, n);
}

// round 12
// speedup vs baseline: 1.3985x; 1.3353x over previous
#include <cuda_runtime.h>

#define S3_EPS 1e-6f
#define PI_F     3.14159265358979f
#define HALFPI_F 1.57079632679490f
#define TPB 256

struct Sim3 { float tx,ty,tz, qx,qy,qz,qw, s; };

__device__ __forceinline__ Sim3 ld_sim3(const float4* __restrict__ p, int i) {
    float4 a = __ldg(p + 2 * i);
    float4 b = __ldg(p + 2 * i + 1);
    Sim3 T = {a.x, a.y, a.z, a.w, b.x, b.y, b.z, b.w};
    return T;
}

__device__ __forceinline__ Sim3 mk_sim3(float4 a, float4 b) {
    Sim3 T = {a.x, a.y, a.z, a.w, b.x, b.y, b.z, b.w};
    return T;
}

__device__ __forceinline__ void cp_async16(void* smem_dst, const void* gmem_src) {
    unsigned s = (unsigned)__cvta_generic_to_shared(smem_dst);
    asm volatile("cp.async.ca.shared.global [%0], [%1], 16;"
                 :: "r"(s), "l"(gmem_src) : "memory");
}

// atan2(y, x) for y >= 0, result in [0, pi]. ~1e-6 abs error.
__device__ __forceinline__ float fast_atan2_pos(float y, float x) {
    float ax  = fabsf(x);
    float num = fminf(y, ax);
    float den = fmaxf(y, ax);
    float r   = __fdividef(num, den);
    float r2  = r * r;
    float p = -0.0117212f;
    p = fmaf(p, r2,  0.05265332f);
    p = fmaf(p, r2, -0.11643287f);
    p = fmaf(p, r2,  0.19354346f);
    p = fmaf(p, r2, -0.33262347f);
    p = fmaf(p, r2,  0.99997726f);
    float t = p * r;
    if (y > ax)    t = HALFPI_F - t;
    if (x < 0.0f)  t = PI_F - t;
    return t;
}

__device__ __forceinline__ void qrot(float qx, float qy, float qz, float qw,
                                     float vx, float vy, float vz,
                                     float& ox, float& oy, float& oz) {
    float ux = qy * vz - qz * vy;
    float uy = qz * vx - qx * vz;
    float uz = qx * vy - qy * vx;
    float cx = qy * uz - qz * uy;
    float cy = qz * ux - qx * uz;
    float cz = qx * uy - qy * ux;
    ox = vx + 2.0f * (qw * ux + cx);
    oy = vy + 2.0f * (qw * uy + cy);
    oz = vz + 2.0f * (qw * uz + cz);
}

__device__ __forceinline__ Sim3 sim3_inv(const Sim3 T) {
    Sim3 R;
    R.qx = -T.qx; R.qy = -T.qy; R.qz = -T.qz; R.qw = T.qw;
    R.s = __fdividef(1.0f, T.s);
    float rx, ry, rz;
    qrot(R.qx, R.qy, R.qz, R.qw, T.tx, T.ty, T.tz, rx, ry, rz);
    R.tx = -R.s * rx; R.ty = -R.s * ry; R.tz = -R.s * rz;
    return R;
}

__device__ __forceinline__ Sim3 sim3_mul(const Sim3 A, const Sim3 B) {
    Sim3 R;
    float rx, ry, rz;
    qrot(A.qx, A.qy, A.qz, A.qw, B.tx, B.ty, B.tz, rx, ry, rz);
    R.tx = A.tx + A.s * rx;
    R.ty = A.ty + A.s * ry;
    R.tz = A.tz + A.s * rz;
    R.qx = A.qw * B.qx + A.qx * B.qw + A.qy * B.qz - A.qz * B.qy;
    R.qy = A.qw * B.qy - A.qx * B.qz + A.qy * B.qw + A.qz * B.qx;
    R.qz = A.qw * B.qz + A.qx * B.qy - A.qy * B.qx + A.qz * B.qw;
    R.qw = A.qw * B.qw - A.qx * B.qx - A.qy * B.qy - A.qz * B.qz;
    R.s = A.s * B.s;
    return R;
}

__device__ __forceinline__ void sim3_log(const Sim3 T, float r[7]) {
    const float vx = T.qx, vy = T.qy, vz = T.qz, qw = T.qw;
    float nv2 = vx * vx + vy * vy + vz * vz;
    float nv = sqrtf(nv2);
    float theta_r = 2.0f * fast_atan2_pos(nv, qw);
    bool small_r = nv < S3_EPS;
    float fac = small_r ? 2.0f : __fdividef(theta_r, nv);
    float px = fac * vx, py = fac * vy, pz = fac * vz;   // phi
    float sigma = __logf(T.s);
    float theta = fac * nv;                              // == |phi|

    bool sig_small = fabsf(sigma) < S3_EPS;
    bool th_small  = theta < S3_EPS;
    float sg = sig_small ? 1.0f : sigma;
    float th = th_small  ? 1.0f : theta;
    float scale = T.s;
    float th2 = th * th, sg2 = sg * sg;

    float snth, csth;
    __sincosf(th, &snth, &csth);

    float rsg  = __fdividef(1.0f, sg);
    float rth  = __fdividef(1.0f, th);
    float rth2 = rth * rth;

    float C    = sig_small ? 1.0f : (scale - 1.0f) * rsg;
    float A_ss = th_small ? 0.5f          : (1.0f - csth) * rth2;
    float B_ss = th_small ? (1.0f / 6.0f) : (th - snth) * rth2 * rth;
    float a = scale * snth;
    float b = scale * csth;
    float c = th2 + sg2;
    float rc = __fdividef(1.0f, c);
    float A_g = (a * sg + (1.0f - b) * th) * rth * rc;
    float B_g = (C - ((b - 1.0f) * sg + a * th) * rc) * rth2;
    float rsg2 = rsg * rsg;
    float A_ts = ((sg - 1.0f) * scale + 1.0f) * rsg2;
    float B_ts = (scale * (sg2 - 2.0f * sg + 2.0f) - 2.0f) * 0.5f * rsg2 * rsg;
    float A = sig_small ? A_ss : (th_small ? A_ts : A_g);
    float B = sig_small ? B_ss : (th_small ? B_ts : B_g);

    // W = C*I + A*skew(phi) + B*(phi phi^T - |phi|^2 I)
    float pp = px * px + py * py + pz * pz;
    float d  = C - B * pp;
    float m00 = d + B * px * px;
    float m11 = d + B * py * py;
    float m22 = d + B * pz * pz;
    float Bxy = B * px * py, Bxz = B * px * pz, Byz = B * py * pz;
    float Ax = A * px, Ay = A * py, Az = A * pz;
    float m01 = Bxy - Az, m10 = Bxy + Az;
    float m02 = Bxz + Ay, m20 = Bxz - Ay;
    float m12 = Byz - Ax, m21 = Byz + Ax;

    float a00 = m11 * m22 - m12 * m21;
    float a01 = m02 * m21 - m01 * m22;
    float a02 = m01 * m12 - m02 * m11;
    float a10 = m12 * m20 - m10 * m22;
    float a11 = m00 * m22 - m02 * m20;
    float a12 = m02 * m10 - m00 * m12;
    float a20 = m10 * m21 - m11 * m20;
    float a21 = m01 * m20 - m00 * m21;
    float a22 = m00 * m11 - m01 * m10;
    float det = m00 * a00 + m01 * a10 + m02 * a20;
    float rdet = __fdividef(1.0f, det);

    r[0] = (a00 * T.tx + a01 * T.ty + a02 * T.tz) * rdet;
    r[1] = (a10 * T.tx + a11 * T.ty + a12 * T.tz) * rdet;
    r[2] = (a20 * T.tx + a21 * T.ty + a22 * T.tz) * rdet;
    r[3] = px;
    r[4] = py;
    r[5] = pz;
    r[6] = sigma;
}

__global__ void __launch_bounds__(TPB)
pgo_residual_kernel(const float4* __restrict__ Twc,
                    const float4* __restrict__ Twc_prior_inv,
                    const float4* __restrict__ Todom_inv,
                    const float* __restrict__ prior_w,
                    const float* __restrict__ odom_w,
                    const int2* __restrict__ edges,
                    const float4* __restrict__ T_lc,
                    float* __restrict__ out,
                    int n) {
    // Per-thread gather slots: lane-contiguous 16B halves -> conflict-free.
    __shared__ float4 sA0[TPB], sA1[TPB];
    __shared__ float4 sB0[TPB], sB1[TPB];
    __shared__ float4 sL0[TPB], sL1[TPB];

    const int tid = threadIdx.x;
    const int i = blockIdx.x * TPB + tid;
    if (i >= n) return;   // no __syncthreads below; per-thread smem only

    // Kick off the dependent gather chain via cp.async: the in-flight data
    // occupies NO registers while the prior/odom math below runs.
    int2 e = __ldg(edges + i);
    cp_async16(&sA0[tid], Twc + 2 * e.x);
    cp_async16(&sA1[tid], Twc + 2 * e.x + 1);
    cp_async16(&sB0[tid], Twc + 2 * e.y);
    cp_async16(&sB1[tid], Twc + 2 * e.y + 1);
    cp_async16(&sL0[tid], T_lc + 2 * i);
    cp_async16(&sL1[tid], T_lc + 2 * i + 1);

    Sim3 Ti = ld_sim3(Twc, i);
    Sim3 Tj = ld_sim3(Twc, i + 1);
    Sim3 delta = sim3_mul(sim3_inv(Ti), Tj);

    float acc[7];
    float tmp[7];

    // r_prior
    sim3_log(sim3_mul(delta, ld_sim3(Twc_prior_inv, i)), tmp);
    #pragma unroll
    for (int k = 0; k < 7; k++)
        acc[k] = tmp[k] * __ldg(prior_w + 7 * i + k);

    // r_odom
    sim3_log(sim3_mul(delta, ld_sim3(Todom_inv, i)), tmp);
    #pragma unroll
    for (int k = 0; k < 7; k++)
        acc[k] += tmp[k] * __ldg(odom_w + 7 * i + k);

    // r_lc: gathers have landed by now (own-thread data only, no block barrier).
    asm volatile("cp.async.wait_all;" ::: "memory");
    Sim3 Ta  = mk_sim3(sA0[tid], sA1[tid]);
    Sim3 Tb  = mk_sim3(sB0[tid], sB1[tid]);
    Sim3 Tlc = mk_sim3(sL0[tid], sL1[tid]);
    Sim3 dlc = sim3_mul(sim3_inv(Ta), Tb);
    sim3_log(sim3_mul(dlc, Tlc), tmp);
    #pragma unroll
    for (int k = 0; k < 7; k++)
        acc[k] += tmp[k];

    #pragma unroll
    for (int k = 0; k < 7; k++)
        out[7 * i + k] = acc[k];
}

extern "C" void kernel_launch(void* const* d_in, const int* in_sizes, int n_in,
                              void* d_out, int out_size) {
    const float4* Twc           = (const float4*)d_in[0];
    const float4* Twc_prior_inv = (const float4*)d_in[1];
    const float4* Todom_inv     = (const float4*)d_in[2];
    const float*  prior_w       = (const float*)d_in[3];
    const float*  odom_w        = (const float*)d_in[4];
    const int2*   edges         = (const int2*)d_in[5];
    const float4* T_lc          = (const float4*)d_in[6];
    float* out = (float*)d_out;

    int n = in_sizes[3] / 7;   // (N_FRAME-1) rows
    int blocks = (n + TPB - 1) / TPB;
    pgo_residual_kernel<<<blocks, TPB>>>(Twc, Twc_prior_inv, Todom_inv,
                                         prior_w, odom_w, edges, T_lc,
                                         out, n);
}